// round 1
// baseline (speedup 1.0000x reference)
#include <cuda_runtime.h>

#define NN 50000
#define HID 128
#define INDIM 16
#define OUTDIM 4
#define MAXE 600000

// ---- scratch (static device globals; no runtime allocation) ----
__device__ float g_agg[NN * HID];     // aggregation accumulator (also used as [NN][16] for layer 1)
__device__ float g_hA[NN * HID];
__device__ float g_hB[NN * HID];
__device__ int   g_src[MAXE];
__device__ int   g_dst[MAXE];
__device__ int   g_deg[NN];
__device__ float g_invdeg[NN];
__device__ int   g_is64;

// ---------------------------------------------------------------
// dtype detection: int64 edge_index has all-zero hi words at odd
// 32-bit positions. int32 random node ids (fixed seed) cannot have
// 64 consecutive zero odd words. Deterministic for given inputs.
// ---------------------------------------------------------------
__global__ void detect_kernel(const int* __restrict__ w) {
    __shared__ int anynz;
    if (threadIdx.x == 0) anynz = 0;
    __syncthreads();
    if (w[2 * threadIdx.x + 1] != 0) atomicOr(&anynz, 1);
    __syncthreads();
    if (threadIdx.x == 0) g_is64 = anynz ? 0 : 1;
}

__global__ void zero_f_kernel(float* __restrict__ p, int n4) {
    int i = blockIdx.x * blockDim.x + threadIdx.x;
    if (i < n4) reinterpret_cast<float4*>(p)[i] = make_float4(0.f, 0.f, 0.f, 0.f);
}

__global__ void zero_i_kernel(int* __restrict__ p, int n) {
    int i = blockIdx.x * blockDim.x + threadIdx.x;
    if (i < n) p[i] = 0;
}

__global__ void convert_kernel(const int* __restrict__ w, int E) {
    int i = blockIdx.x * blockDim.x + threadIdx.x;
    if (i >= E) return;
    int s, d;
    if (g_is64) { s = w[2 * i]; d = w[2 * (E + i)]; }
    else        { s = w[i];     d = w[E + i];       }
    g_src[i] = s;
    g_dst[i] = d;
    atomicAdd(&g_deg[d], 1);
}

__global__ void invdeg_kernel(int M) {
    int i = blockIdx.x * blockDim.x + threadIdx.x;
    if (i < M) g_invdeg[i] = 1.0f / (float)max(g_deg[i], 1);
}

// ---------------------------------------------------------------
// Scatter for layer 1 (16-dim features): 4 threads per edge, each
// handles one float4 chunk (4 atomic adds).
// ---------------------------------------------------------------
__global__ void scatter16_kernel(const float* __restrict__ x, int E) {
    int t = blockIdx.x * blockDim.x + threadIdx.x;
    if (t >= E * 4) return;
    int e = t >> 2, q = t & 3;
    int s = g_src[e], d = g_dst[e];
    float4 v = *reinterpret_cast<const float4*>(x + (size_t)s * INDIM + q * 4);
    float* dst = g_agg + (size_t)d * INDIM + q * 4;
    atomicAdd(dst + 0, v.x);
    atomicAdd(dst + 1, v.y);
    atomicAdd(dst + 2, v.z);
    atomicAdd(dst + 3, v.w);
}

// ---------------------------------------------------------------
// Scatter for 128-dim features: one warp per edge. Lane l loads
// float4 #l of the 128-float src row, 4 atomic adds to dst row.
// ---------------------------------------------------------------
__global__ void scatter128_kernel(const float* __restrict__ h, int E) {
    int gt = blockIdx.x * blockDim.x + threadIdx.x;
    int e = gt >> 5;
    if (e >= E) return;
    int lane = gt & 31;
    int s = g_src[e], d = g_dst[e];
    float4 v = __ldg(reinterpret_cast<const float4*>(h + (size_t)s * HID) + lane);
    float* dst = g_agg + (size_t)d * HID + lane * 4;
    atomicAdd(dst + 0, v.x);
    atomicAdd(dst + 1, v.y);
    atomicAdd(dst + 2, v.z);
    atomicAdd(dst + 3, v.w);
}

// ---------------------------------------------------------------
// Fused SAGE layer GEMM:
//   C[n][j] = relu( sum_{k<S} agg[n][k]*invdeg[n]*W0[j][k]
//                 + sum_{k<S} A1[n][k]*W1[j][k] + bias[j] )
// M x 128 output, K = 2*S. Tiled SGEMM: BM=64, BN=128, BK=16,
// 256 threads, 4x8 microtile per thread.
// ---------------------------------------------------------------
template <int S>
__global__ void __launch_bounds__(256)
sage_gemm_kernel(const float* __restrict__ A0, const float* __restrict__ A1,
                 const float* __restrict__ W0, const float* __restrict__ W1,
                 const float* __restrict__ bias, float* __restrict__ C, int M) {
    __shared__ float As[16][64];
    __shared__ float Bs[16][128];

    const int tid = threadIdx.x;
    const int blockM = blockIdx.x * 64;
    const int tr = tid >> 4;      // 0..15 (row group)
    const int tc = tid & 15;      // 0..15 (col group)

    // A-loader coords: thread -> (row lm, k-quad kq)
    const int lm = tid >> 2;          // 0..63
    const int kq = (tid & 3) * 4;     // 0,4,8,12
    const int node = blockM + lm;
    // B-loader coords: thread -> (out j, k-octet bkq)
    const int bj = tid >> 1;          // 0..127
    const int bkq = (tid & 1) * 8;    // 0 or 8

    float acc[4][8];
#pragma unroll
    for (int i = 0; i < 4; i++)
#pragma unroll
        for (int j = 0; j < 8; j++) acc[i][j] = 0.f;

    const int K = 2 * S;
#pragma unroll
    for (int k0 = 0; k0 < K; k0 += 16) {
        const int half = (k0 >= S);
        const float* Ab = half ? A1 : A0;
        const float* Wb = half ? W1 : W0;
        const int koff = k0 - (half ? S : 0);

        float4 va = make_float4(0.f, 0.f, 0.f, 0.f);
        if (node < M) {
            va = *reinterpret_cast<const float4*>(Ab + (size_t)node * S + koff + kq);
            if (!half) {
                float sc = g_invdeg[node];
                va.x *= sc; va.y *= sc; va.z *= sc; va.w *= sc;
            }
        }
        float4 vb0 = *reinterpret_cast<const float4*>(Wb + (size_t)bj * S + koff + bkq);
        float4 vb1 = *reinterpret_cast<const float4*>(Wb + (size_t)bj * S + koff + bkq + 4);

        __syncthreads();
        As[kq + 0][lm] = va.x;
        As[kq + 1][lm] = va.y;
        As[kq + 2][lm] = va.z;
        As[kq + 3][lm] = va.w;
        Bs[bkq + 0][bj] = vb0.x;
        Bs[bkq + 1][bj] = vb0.y;
        Bs[bkq + 2][bj] = vb0.z;
        Bs[bkq + 3][bj] = vb0.w;
        Bs[bkq + 4][bj] = vb1.x;
        Bs[bkq + 5][bj] = vb1.y;
        Bs[bkq + 6][bj] = vb1.z;
        Bs[bkq + 7][bj] = vb1.w;
        __syncthreads();

#pragma unroll
        for (int k = 0; k < 16; k++) {
            float4 a = *reinterpret_cast<float4*>(&As[k][tr * 4]);
            float4 b0 = *reinterpret_cast<float4*>(&Bs[k][tc * 8]);
            float4 b1 = *reinterpret_cast<float4*>(&Bs[k][tc * 8 + 4]);
            float av[4] = {a.x, a.y, a.z, a.w};
            float bv[8] = {b0.x, b0.y, b0.z, b0.w, b1.x, b1.y, b1.z, b1.w};
#pragma unroll
            for (int i = 0; i < 4; i++)
#pragma unroll
                for (int j = 0; j < 8; j++) acc[i][j] += av[i] * bv[j];
        }
    }

    // epilogue: bias + relu
    float4 bb0 = *reinterpret_cast<const float4*>(bias + tc * 8);
    float4 bb1 = *reinterpret_cast<const float4*>(bias + tc * 8 + 4);
    float bb[8] = {bb0.x, bb0.y, bb0.z, bb0.w, bb1.x, bb1.y, bb1.z, bb1.w};
#pragma unroll
    for (int i = 0; i < 4; i++) {
        int n = blockM + tr * 4 + i;
        if (n < M) {
            float4 o0, o1;
            o0.x = fmaxf(acc[i][0] + bb[0], 0.f);
            o0.y = fmaxf(acc[i][1] + bb[1], 0.f);
            o0.z = fmaxf(acc[i][2] + bb[2], 0.f);
            o0.w = fmaxf(acc[i][3] + bb[3], 0.f);
            o1.x = fmaxf(acc[i][4] + bb[4], 0.f);
            o1.y = fmaxf(acc[i][5] + bb[5], 0.f);
            o1.z = fmaxf(acc[i][6] + bb[6], 0.f);
            o1.w = fmaxf(acc[i][7] + bb[7], 0.f);
            *reinterpret_cast<float4*>(C + (size_t)n * HID + tc * 8) = o0;
            *reinterpret_cast<float4*>(C + (size_t)n * HID + tc * 8 + 4) = o1;
        }
    }
}

// ---------------------------------------------------------------
// Final projection: out[n][j] = h[n] . Wh[j] + bh[j], one warp/node.
// ---------------------------------------------------------------
__global__ void final_kernel(const float* __restrict__ h, const float* __restrict__ Wh,
                             const float* __restrict__ bh, float* __restrict__ out, int M) {
    __shared__ float Ws[OUTDIM * HID];
    __shared__ float bs[OUTDIM];
    int tid = threadIdx.x;
    for (int i = tid; i < OUTDIM * HID; i += blockDim.x) Ws[i] = Wh[i];
    if (tid < OUTDIM) bs[tid] = bh[tid];
    __syncthreads();

    int gw = (blockIdx.x * blockDim.x + tid) >> 5;
    int lane = tid & 31;
    if (gw >= M) return;

    float4 hv = *reinterpret_cast<const float4*>(h + (size_t)gw * HID + lane * 4);
#pragma unroll
    for (int j = 0; j < OUTDIM; j++) {
        const float* wr = Ws + j * HID + lane * 4;
        float p = hv.x * wr[0] + hv.y * wr[1] + hv.z * wr[2] + hv.w * wr[3];
#pragma unroll
        for (int off = 16; off > 0; off >>= 1)
            p += __shfl_down_sync(0xffffffffu, p, off);
        if (lane == 0) out[gw * OUTDIM + j] = p + bs[j];
    }
}

// ---------------------------------------------------------------
extern "C" void kernel_launch(void* const* d_in, const int* in_sizes, int n_in,
                              void* d_out, int out_size) {
    (void)n_in; (void)out_size;
    const float* x   = (const float*)d_in[0];
    const int*   ei  = (const int*)d_in[1];
    const float* Wl1 = (const float*)d_in[2];
    const float* Wr1 = (const float*)d_in[3];
    const float* b1  = (const float*)d_in[4];
    const float* Wl2 = (const float*)d_in[5];
    const float* Wr2 = (const float*)d_in[6];
    const float* b2  = (const float*)d_in[7];
    const float* Wl3 = (const float*)d_in[8];
    const float* Wr3 = (const float*)d_in[9];
    const float* b3  = (const float*)d_in[10];
    const float* Wh  = (const float*)d_in[11];
    const float* bh  = (const float*)d_in[12];
    float* out = (float*)d_out;

    const int M = in_sizes[0] / INDIM;   // 50000
    const int E = in_sizes[1] / 2;       // 600000 (element count same for i32/i64)

    float *agg, *hA, *hB;
    int* deg;
    cudaGetSymbolAddress((void**)&agg, g_agg);
    cudaGetSymbolAddress((void**)&hA, g_hA);
    cudaGetSymbolAddress((void**)&hB, g_hB);
    cudaGetSymbolAddress((void**)&deg, g_deg);

    const int T = 256;

    // edge preprocessing
    detect_kernel<<<1, 64>>>(ei);
    zero_i_kernel<<<(M + T - 1) / T, T>>>(deg, M);
    convert_kernel<<<(E + T - 1) / T, T>>>(ei, E);
    invdeg_kernel<<<(M + T - 1) / T, T>>>(M);

    const int gemmBlocks = (M + 63) / 64;

    // ---- layer 1 (16 -> 128) ----
    zero_f_kernel<<<((M * INDIM / 4) + T - 1) / T, T>>>(agg, M * INDIM / 4);
    scatter16_kernel<<<((E * 4) + T - 1) / T, T>>>(x, E);
    sage_gemm_kernel<INDIM><<<gemmBlocks, 256>>>(agg, x, Wl1, Wr1, b1, hA, M);

    // ---- layer 2 (128 -> 128) ----
    zero_f_kernel<<<((M * HID / 4) + T - 1) / T, T>>>(agg, M * HID / 4);
    scatter128_kernel<<<((E * 32) + T - 1) / T, T>>>(hA, E);
    sage_gemm_kernel<HID><<<gemmBlocks, 256>>>(agg, hA, Wl2, Wr2, b2, hB, M);

    // ---- layer 3 (128 -> 128) ----
    zero_f_kernel<<<((M * HID / 4) + T - 1) / T, T>>>(agg, M * HID / 4);
    scatter128_kernel<<<((E * 32) + T - 1) / T, T>>>(hB, E);
    sage_gemm_kernel<HID><<<gemmBlocks, 256>>>(agg, hB, Wl3, Wr3, b3, hA, M);

    // ---- final projection (128 -> 4) ----
    final_kernel<<<((M * 32) + T - 1) / T, T>>>(hA, Wh, bh, out, M);
}

// round 2
// speedup vs baseline: 1.4956x; 1.4956x over previous
#include <cuda_runtime.h>

#define NN 50000
#define HID 128
#define INDIM 16
#define OUTDIM 4
#define MAXE 600000

// ---- scratch (static device globals; no runtime allocation) ----
__device__ float g_agg[NN * HID];
__device__ float g_hA[NN * HID];
__device__ float g_hB[NN * HID];
__device__ int   g_src[MAXE];
__device__ int   g_dst[MAXE];
__device__ int   g_csrc[MAXE];       // CSR: src ids sorted by dst
__device__ int   g_deg[NN];
__device__ int   g_rowstart[NN + 1];
__device__ int   g_cursor[NN];
__device__ int   g_is64;

// ---------------------------------------------------------------
// dtype detection: int64 edge_index has all-zero hi words at odd
// 32-bit positions (node ids < 2^31). Deterministic for fixed input.
// ---------------------------------------------------------------
__global__ void detect_kernel(const int* __restrict__ w) {
    __shared__ int anynz;
    if (threadIdx.x == 0) anynz = 0;
    __syncthreads();
    if (w[2 * threadIdx.x + 1] != 0) atomicOr(&anynz, 1);
    __syncthreads();
    if (threadIdx.x == 0) g_is64 = anynz ? 0 : 1;
}

__global__ void zero_i_kernel(int* __restrict__ p, int n) {
    int i = blockIdx.x * blockDim.x + threadIdx.x;
    if (i < n) p[i] = 0;
}

__global__ void convert_kernel(const int* __restrict__ w, int E) {
    int i = blockIdx.x * blockDim.x + threadIdx.x;
    if (i >= E) return;
    int s, d;
    if (g_is64) { s = w[2 * i]; d = w[2 * (E + i)]; }
    else        { s = w[i];     d = w[E + i];       }
    g_src[i] = s;
    g_dst[i] = d;
    atomicAdd(&g_deg[d], 1);
}

// ---------------------------------------------------------------
// One-block exclusive scan over degrees -> rowstart + cursor copy.
// ---------------------------------------------------------------
__global__ void scan_kernel(int M) {
    __shared__ int part[1024];
    int t = threadIdx.x;
    int chunk = (M + 1023) / 1024;
    int lo = t * chunk;
    int hi = min(lo + chunk, M);
    int s = 0;
    for (int i = lo; i < hi; i++) s += g_deg[i];
    part[t] = s;
    __syncthreads();
    for (int off = 1; off < 1024; off <<= 1) {
        int v = (t >= off) ? part[t - off] : 0;
        __syncthreads();
        part[t] += v;
        __syncthreads();
    }
    int run = (t > 0) ? part[t - 1] : 0;
    for (int i = lo; i < hi; i++) {
        int d = g_deg[i];
        g_rowstart[i] = run;
        g_cursor[i] = run;
        run += d;
    }
    if (t == 0) g_rowstart[M] = part[1023];
}

__global__ void fill_kernel(int E) {
    int i = blockIdx.x * blockDim.x + threadIdx.x;
    if (i >= E) return;
    int d = g_dst[i];
    int pos = atomicAdd(&g_cursor[d], 1);
    g_csrc[pos] = g_src[i];
}

// ---------------------------------------------------------------
// CSR mean-gather, 128-dim: one warp per node, lane = float4 chunk.
// No atomics; invdeg folded in.
// ---------------------------------------------------------------
__global__ void gather128_kernel(const float* __restrict__ h, float* __restrict__ agg, int M) {
    int gt = blockIdx.x * blockDim.x + threadIdx.x;
    int n = gt >> 5;
    if (n >= M) return;
    int lane = gt & 31;
    int rs0 = g_rowstart[n], rs1 = g_rowstart[n + 1];
    float4 acc = make_float4(0.f, 0.f, 0.f, 0.f);
    int i = rs0;
    for (; i + 4 <= rs1; i += 4) {
        int s0 = g_csrc[i + 0];
        int s1 = g_csrc[i + 1];
        int s2 = g_csrc[i + 2];
        int s3 = g_csrc[i + 3];
        float4 v0 = __ldg(reinterpret_cast<const float4*>(h + (size_t)s0 * HID) + lane);
        float4 v1 = __ldg(reinterpret_cast<const float4*>(h + (size_t)s1 * HID) + lane);
        float4 v2 = __ldg(reinterpret_cast<const float4*>(h + (size_t)s2 * HID) + lane);
        float4 v3 = __ldg(reinterpret_cast<const float4*>(h + (size_t)s3 * HID) + lane);
        acc.x += v0.x + v1.x + v2.x + v3.x;
        acc.y += v0.y + v1.y + v2.y + v3.y;
        acc.z += v0.z + v1.z + v2.z + v3.z;
        acc.w += v0.w + v1.w + v2.w + v3.w;
    }
    for (; i < rs1; i++) {
        int s0 = g_csrc[i];
        float4 v0 = __ldg(reinterpret_cast<const float4*>(h + (size_t)s0 * HID) + lane);
        acc.x += v0.x; acc.y += v0.y; acc.z += v0.z; acc.w += v0.w;
    }
    float sc = 1.0f / (float)max(rs1 - rs0, 1);
    acc.x *= sc; acc.y *= sc; acc.z *= sc; acc.w *= sc;
    reinterpret_cast<float4*>(agg + (size_t)n * HID)[lane] = acc;
}

// ---------------------------------------------------------------
// CSR mean-gather, 16-dim: 4 threads per node (one float4 each).
// ---------------------------------------------------------------
__global__ void gather16_kernel(const float* __restrict__ x, float* __restrict__ agg, int M) {
    int gt = blockIdx.x * blockDim.x + threadIdx.x;
    int n = gt >> 2;
    if (n >= M) return;
    int q = gt & 3;
    int rs0 = g_rowstart[n], rs1 = g_rowstart[n + 1];
    float4 acc = make_float4(0.f, 0.f, 0.f, 0.f);
    for (int i = rs0; i < rs1; i++) {
        int s0 = g_csrc[i];
        float4 v = __ldg(reinterpret_cast<const float4*>(x + (size_t)s0 * INDIM) + q);
        acc.x += v.x; acc.y += v.y; acc.z += v.z; acc.w += v.w;
    }
    float sc = 1.0f / (float)max(rs1 - rs0, 1);
    acc.x *= sc; acc.y *= sc; acc.z *= sc; acc.w *= sc;
    reinterpret_cast<float4*>(agg + (size_t)n * INDIM)[q] = acc;
}

// ---------------------------------------------------------------
// Fused SAGE layer GEMM:
//   C[n][j] = relu( agg[n,:].W0[j,:] + A1[n,:].W1[j,:] + bias[j] )
// BM=128, BN=128, BK=8, 256 threads, 8x8 microtile.
// ---------------------------------------------------------------
template <int S>
__global__ void __launch_bounds__(256)
sage_gemm_kernel(const float* __restrict__ A0, const float* __restrict__ A1,
                 const float* __restrict__ W0, const float* __restrict__ W1,
                 const float* __restrict__ bias, float* __restrict__ C, int M) {
    __shared__ float As[8][128];
    __shared__ float Bs[8][128];

    const int tid = threadIdx.x;
    const int m0 = blockIdx.x * 128;
    const int lm = tid >> 1;            // 0..127 row (A) / out-col (B)
    const int kq = (tid & 1) * 4;       // 0 or 4
    const int node = m0 + lm;
    const int tr = tid >> 4;            // 0..15
    const int tc = tid & 15;            // 0..15

    float acc[8][8];
#pragma unroll
    for (int i = 0; i < 8; i++)
#pragma unroll
        for (int j = 0; j < 8; j++) acc[i][j] = 0.f;

    const int K = 2 * S;
#pragma unroll 2
    for (int k0 = 0; k0 < K; k0 += 8) {
        const bool half = (k0 >= S);
        const float* Ab = half ? A1 : A0;
        const float* Wb = half ? W1 : W0;
        const int koff = (half ? k0 - S : k0) + kq;

        float4 va = make_float4(0.f, 0.f, 0.f, 0.f);
        if (node < M)
            va = *reinterpret_cast<const float4*>(Ab + (size_t)node * S + koff);
        float4 vb = *reinterpret_cast<const float4*>(Wb + (size_t)lm * S + koff);

        __syncthreads();
        As[kq + 0][lm] = va.x;
        As[kq + 1][lm] = va.y;
        As[kq + 2][lm] = va.z;
        As[kq + 3][lm] = va.w;
        Bs[kq + 0][lm] = vb.x;
        Bs[kq + 1][lm] = vb.y;
        Bs[kq + 2][lm] = vb.z;
        Bs[kq + 3][lm] = vb.w;
        __syncthreads();

#pragma unroll
        for (int k = 0; k < 8; k++) {
            float4 a0 = *reinterpret_cast<float4*>(&As[k][tr * 8]);
            float4 a1 = *reinterpret_cast<float4*>(&As[k][tr * 8 + 4]);
            float4 b0 = *reinterpret_cast<float4*>(&Bs[k][tc * 8]);
            float4 b1 = *reinterpret_cast<float4*>(&Bs[k][tc * 8 + 4]);
            float av[8] = {a0.x, a0.y, a0.z, a0.w, a1.x, a1.y, a1.z, a1.w};
            float bv[8] = {b0.x, b0.y, b0.z, b0.w, b1.x, b1.y, b1.z, b1.w};
#pragma unroll
            for (int i = 0; i < 8; i++)
#pragma unroll
                for (int j = 0; j < 8; j++) acc[i][j] += av[i] * bv[j];
        }
    }

    // epilogue: bias + relu
    float4 bb0 = *reinterpret_cast<const float4*>(bias + tc * 8);
    float4 bb1 = *reinterpret_cast<const float4*>(bias + tc * 8 + 4);
    float bb[8] = {bb0.x, bb0.y, bb0.z, bb0.w, bb1.x, bb1.y, bb1.z, bb1.w};
#pragma unroll
    for (int i = 0; i < 8; i++) {
        int n = m0 + tr * 8 + i;
        if (n < M) {
            float4 o0, o1;
            o0.x = fmaxf(acc[i][0] + bb[0], 0.f);
            o0.y = fmaxf(acc[i][1] + bb[1], 0.f);
            o0.z = fmaxf(acc[i][2] + bb[2], 0.f);
            o0.w = fmaxf(acc[i][3] + bb[3], 0.f);
            o1.x = fmaxf(acc[i][4] + bb[4], 0.f);
            o1.y = fmaxf(acc[i][5] + bb[5], 0.f);
            o1.z = fmaxf(acc[i][6] + bb[6], 0.f);
            o1.w = fmaxf(acc[i][7] + bb[7], 0.f);
            *reinterpret_cast<float4*>(C + (size_t)n * HID + tc * 8) = o0;
            *reinterpret_cast<float4*>(C + (size_t)n * HID + tc * 8 + 4) = o1;
        }
    }
}

// ---------------------------------------------------------------
// Final projection: out[n][j] = h[n] . Wh[j] + bh[j], one warp/node.
// ---------------------------------------------------------------
__global__ void final_kernel(const float* __restrict__ h, const float* __restrict__ Wh,
                             const float* __restrict__ bh, float* __restrict__ out, int M) {
    __shared__ float Ws[OUTDIM * HID];
    __shared__ float bs[OUTDIM];
    int tid = threadIdx.x;
    for (int i = tid; i < OUTDIM * HID; i += blockDim.x) Ws[i] = Wh[i];
    if (tid < OUTDIM) bs[tid] = bh[tid];
    __syncthreads();

    int gw = (blockIdx.x * blockDim.x + tid) >> 5;
    int lane = tid & 31;
    if (gw >= M) return;

    float4 hv = *reinterpret_cast<const float4*>(h + (size_t)gw * HID + lane * 4);
#pragma unroll
    for (int j = 0; j < OUTDIM; j++) {
        const float* wr = Ws + j * HID + lane * 4;
        float p = hv.x * wr[0] + hv.y * wr[1] + hv.z * wr[2] + hv.w * wr[3];
#pragma unroll
        for (int off = 16; off > 0; off >>= 1)
            p += __shfl_down_sync(0xffffffffu, p, off);
        if (lane == 0) out[gw * OUTDIM + j] = p + bs[j];
    }
}

// ---------------------------------------------------------------
extern "C" void kernel_launch(void* const* d_in, const int* in_sizes, int n_in,
                              void* d_out, int out_size) {
    (void)n_in; (void)out_size;
    const float* x   = (const float*)d_in[0];
    const int*   ei  = (const int*)d_in[1];
    const float* Wl1 = (const float*)d_in[2];
    const float* Wr1 = (const float*)d_in[3];
    const float* b1  = (const float*)d_in[4];
    const float* Wl2 = (const float*)d_in[5];
    const float* Wr2 = (const float*)d_in[6];
    const float* b2  = (const float*)d_in[7];
    const float* Wl3 = (const float*)d_in[8];
    const float* Wr3 = (const float*)d_in[9];
    const float* b3  = (const float*)d_in[10];
    const float* Wh  = (const float*)d_in[11];
    const float* bh  = (const float*)d_in[12];
    float* out = (float*)d_out;

    const int M = in_sizes[0] / INDIM;   // 50000
    const int E = in_sizes[1] / 2;       // 600000

    float *agg, *hA, *hB;
    int* deg;
    cudaGetSymbolAddress((void**)&agg, g_agg);
    cudaGetSymbolAddress((void**)&hA, g_hA);
    cudaGetSymbolAddress((void**)&hB, g_hB);
    cudaGetSymbolAddress((void**)&deg, g_deg);

    const int T = 256;

    // ---- CSR build ----
    detect_kernel<<<1, 64>>>(ei);
    zero_i_kernel<<<(M + T - 1) / T, T>>>(deg, M);
    convert_kernel<<<(E + T - 1) / T, T>>>(ei, E);
    scan_kernel<<<1, 1024>>>(M);
    fill_kernel<<<(E + T - 1) / T, T>>>(E);

    const int gemmBlocks = (M + 127) / 128;

    // ---- layer 1 (16 -> 128) ----
    gather16_kernel<<<((M * 4) + T - 1) / T, T>>>(x, agg, M);
    sage_gemm_kernel<INDIM><<<gemmBlocks, 256>>>(agg, x, Wl1, Wr1, b1, hA, M);

    // ---- layer 2 (128 -> 128) ----
    gather128_kernel<<<((M * 32) + T - 1) / T, T>>>(hA, agg, M);
    sage_gemm_kernel<HID><<<gemmBlocks, 256>>>(agg, hA, Wl2, Wr2, b2, hB, M);

    // ---- layer 3 (128 -> 128) ----
    gather128_kernel<<<((M * 32) + T - 1) / T, T>>>(hB, agg, M);
    sage_gemm_kernel<HID><<<gemmBlocks, 256>>>(agg, hB, Wl3, Wr3, b3, hA, M);

    // ---- final projection (128 -> 4) ----
    final_kernel<<<((M * 32) + T - 1) / T, T>>>(hA, Wh, bh, out, M);
}

// round 3
// speedup vs baseline: 1.8602x; 1.2438x over previous
#include <cuda_runtime.h>

#define NN 50000
#define HID 128
#define INDIM 16
#define OUTDIM 4
#define MAXE 600000
#define SCAN_CHUNK 1024
#define MAX_SCAN_BLOCKS 128

// ---- scratch (static device globals; no runtime allocation) ----
__device__ float g_agg[NN * HID];
__device__ float g_hA[NN * HID];
__device__ float g_hB[NN * HID];
__device__ int   g_src[MAXE];
__device__ int   g_dst[MAXE];
__device__ int   g_csrc[MAXE];       // CSR: src ids sorted by dst
__device__ int   g_deg[NN];
__device__ int   g_rowstart[NN + 1];
__device__ int   g_cursor[NN];
__device__ int   g_blocksum[MAX_SCAN_BLOCKS];
__device__ int   g_blockoff[MAX_SCAN_BLOCKS];
__device__ int   g_is64;

// ---------------------------------------------------------------
// dtype detection: int64 edge_index has all-zero hi words at odd
// 32-bit positions (node ids < 2^31). Deterministic for fixed input.
// ---------------------------------------------------------------
__global__ void detect_kernel(const int* __restrict__ w) {
    __shared__ int anynz;
    if (threadIdx.x == 0) anynz = 0;
    __syncthreads();
    if (w[2 * threadIdx.x + 1] != 0) atomicOr(&anynz, 1);
    __syncthreads();
    if (threadIdx.x == 0) g_is64 = anynz ? 0 : 1;
}

__global__ void zero_i_kernel(int* __restrict__ p, int n) {
    int i = blockIdx.x * blockDim.x + threadIdx.x;
    if (i < n) p[i] = 0;
}

__global__ void convert_kernel(const int* __restrict__ w, int E) {
    int i = blockIdx.x * blockDim.x + threadIdx.x;
    if (i >= E) return;
    int s, d;
    if (g_is64) { s = w[2 * i]; d = w[2 * (E + i)]; }
    else        { s = w[i];     d = w[E + i];       }
    g_src[i] = s;
    g_dst[i] = d;
    atomicAdd(&g_deg[d], 1);
}

// ---------------------------------------------------------------
// Hierarchical exclusive scan of g_deg -> g_rowstart/g_cursor.
// Phase 1: per-block (1024 elems) totals. Phase 2: scan totals.
// Phase 3: intra-block scan + offset, write results.
// ---------------------------------------------------------------
__device__ __forceinline__ void block_scan_1024(int M, int& thread_sum, int& thread_excl, int* warp_buf) {
    // thread handles 4 consecutive ints; compute exclusive prefix of thread_sum
    int t = threadIdx.x;
    int lane = t & 31, w = t >> 5;
    int v = thread_sum;
#pragma unroll
    for (int off = 1; off < 32; off <<= 1) {
        int u = __shfl_up_sync(0xffffffffu, v, off);
        if (lane >= off) v += u;
    }
    if (lane == 31) warp_buf[w] = v;
    __syncthreads();
    if (w == 0) {
        int ws = (lane < 8) ? warp_buf[lane] : 0;
#pragma unroll
        for (int off = 1; off < 8; off <<= 1) {
            int u = __shfl_up_sync(0xffffffffu, ws, off);
            if (lane >= off) ws += u;
        }
        if (lane < 8) warp_buf[lane] = ws;
    }
    __syncthreads();
    thread_excl = v - thread_sum + (w > 0 ? warp_buf[w - 1] : 0);
}

__global__ void scan_phase1(int M) {
    __shared__ int warp_buf[8];
    int b = blockIdx.x, t = threadIdx.x;
    int base = b * SCAN_CHUNK + t * 4;
    int d[4] = {0, 0, 0, 0};
#pragma unroll
    for (int i = 0; i < 4; i++)
        if (base + i < M) d[i] = g_deg[base + i];
    int s = d[0] + d[1] + d[2] + d[3];
    int excl;
    block_scan_1024(M, s, excl, warp_buf);
    if (t == blockDim.x - 1) g_blocksum[b] = excl + s;
}

__global__ void scan_phase2(int NB, int E) {
    int t = threadIdx.x;
    int v = (t < NB) ? g_blocksum[t] : 0;
#pragma unroll
    for (int off = 1; off < 128; off <<= 1) {
        int u = __shfl_up_sync(0xffffffffu, v, off);  // works only within warp
        (void)u;
        break;
    }
    // simple serial scan by thread 0 (NB <= 128, trivial)
    __shared__ int buf[MAX_SCAN_BLOCKS];
    if (t < NB) buf[t] = g_blocksum[t];
    __syncthreads();
    if (t == 0) {
        int run = 0;
        for (int i = 0; i < NB; i++) { int x = buf[i]; buf[i] = run; run += x; }
        g_rowstart[0] = 0;  // safety
    }
    __syncthreads();
    if (t < NB) g_blockoff[t] = buf[t];
}

__global__ void scan_phase3(int M, int E) {
    __shared__ int warp_buf[8];
    int b = blockIdx.x, t = threadIdx.x;
    int base = b * SCAN_CHUNK + t * 4;
    int d[4] = {0, 0, 0, 0};
#pragma unroll
    for (int i = 0; i < 4; i++)
        if (base + i < M) d[i] = g_deg[base + i];
    int s = d[0] + d[1] + d[2] + d[3];
    int excl;
    block_scan_1024(M, s, excl, warp_buf);
    int run = excl + g_blockoff[b];
#pragma unroll
    for (int i = 0; i < 4; i++) {
        if (base + i < M) {
            g_rowstart[base + i] = run;
            g_cursor[base + i] = run;
            run += d[i];
        }
    }
    if (b == 0 && t == 0) g_rowstart[M] = E;
}

__global__ void fill_kernel(int E) {
    int i = blockIdx.x * blockDim.x + threadIdx.x;
    if (i >= E) return;
    int d = g_dst[i];
    int pos = atomicAdd(&g_cursor[d], 1);
    g_csrc[pos] = g_src[i];
}

// ---------------------------------------------------------------
// CSR mean-gather, 128-dim: one warp per node, lane = float4 chunk.
// ---------------------------------------------------------------
__global__ void gather128_kernel(const float* __restrict__ h, float* __restrict__ agg, int M) {
    int gt = blockIdx.x * blockDim.x + threadIdx.x;
    int n = gt >> 5;
    if (n >= M) return;
    int lane = gt & 31;
    int rs0 = g_rowstart[n], rs1 = g_rowstart[n + 1];
    float4 acc = make_float4(0.f, 0.f, 0.f, 0.f);
    int i = rs0;
    for (; i + 4 <= rs1; i += 4) {
        int s0 = g_csrc[i + 0];
        int s1 = g_csrc[i + 1];
        int s2 = g_csrc[i + 2];
        int s3 = g_csrc[i + 3];
        float4 v0 = __ldg(reinterpret_cast<const float4*>(h + (size_t)s0 * HID) + lane);
        float4 v1 = __ldg(reinterpret_cast<const float4*>(h + (size_t)s1 * HID) + lane);
        float4 v2 = __ldg(reinterpret_cast<const float4*>(h + (size_t)s2 * HID) + lane);
        float4 v3 = __ldg(reinterpret_cast<const float4*>(h + (size_t)s3 * HID) + lane);
        acc.x += v0.x + v1.x + v2.x + v3.x;
        acc.y += v0.y + v1.y + v2.y + v3.y;
        acc.z += v0.z + v1.z + v2.z + v3.z;
        acc.w += v0.w + v1.w + v2.w + v3.w;
    }
    for (; i < rs1; i++) {
        int s0 = g_csrc[i];
        float4 v0 = __ldg(reinterpret_cast<const float4*>(h + (size_t)s0 * HID) + lane);
        acc.x += v0.x; acc.y += v0.y; acc.z += v0.z; acc.w += v0.w;
    }
    float sc = 1.0f / (float)max(rs1 - rs0, 1);
    acc.x *= sc; acc.y *= sc; acc.z *= sc; acc.w *= sc;
    reinterpret_cast<float4*>(agg + (size_t)n * HID)[lane] = acc;
}

// ---------------------------------------------------------------
// CSR mean-gather, 16-dim: 4 threads per node (one float4 each).
// ---------------------------------------------------------------
__global__ void gather16_kernel(const float* __restrict__ x, float* __restrict__ agg, int M) {
    int gt = blockIdx.x * blockDim.x + threadIdx.x;
    int n = gt >> 2;
    if (n >= M) return;
    int q = gt & 3;
    int rs0 = g_rowstart[n], rs1 = g_rowstart[n + 1];
    float4 acc = make_float4(0.f, 0.f, 0.f, 0.f);
    for (int i = rs0; i < rs1; i++) {
        int s0 = g_csrc[i];
        float4 v = __ldg(reinterpret_cast<const float4*>(x + (size_t)s0 * INDIM) + q);
        acc.x += v.x; acc.y += v.y; acc.z += v.z; acc.w += v.w;
    }
    float sc = 1.0f / (float)max(rs1 - rs0, 1);
    acc.x *= sc; acc.y *= sc; acc.z *= sc; acc.w *= sc;
    reinterpret_cast<float4*>(agg + (size_t)n * INDIM)[q] = acc;
}

// ---------------------------------------------------------------
// Fused SAGE layer GEMM:
//   C[n][j] = relu( agg[n,:].W0[j,:] + A1[n,:].W1[j,:] + bias[j] )
// BM=128, BN=128, BK=8, 256 threads, 8x8 microtile.
// ---------------------------------------------------------------
template <int S>
__global__ void __launch_bounds__(256)
sage_gemm_kernel(const float* __restrict__ A0, const float* __restrict__ A1,
                 const float* __restrict__ W0, const float* __restrict__ W1,
                 const float* __restrict__ bias, float* __restrict__ C, int M) {
    __shared__ float As[8][128];
    __shared__ float Bs[8][128];

    const int tid = threadIdx.x;
    const int m0 = blockIdx.x * 128;
    const int lm = tid >> 1;            // 0..127 row (A) / out-col (B)
    const int kq = (tid & 1) * 4;       // 0 or 4
    const int node = m0 + lm;
    const int tr = tid >> 4;            // 0..15
    const int tc = tid & 15;            // 0..15

    float acc[8][8];
#pragma unroll
    for (int i = 0; i < 8; i++)
#pragma unroll
        for (int j = 0; j < 8; j++) acc[i][j] = 0.f;

    const int K = 2 * S;
#pragma unroll 2
    for (int k0 = 0; k0 < K; k0 += 8) {
        const bool half = (k0 >= S);
        const float* Ab = half ? A1 : A0;
        const float* Wb = half ? W1 : W0;
        const int koff = (half ? k0 - S : k0) + kq;

        float4 va = make_float4(0.f, 0.f, 0.f, 0.f);
        if (node < M)
            va = *reinterpret_cast<const float4*>(Ab + (size_t)node * S + koff);
        float4 vb = *reinterpret_cast<const float4*>(Wb + (size_t)lm * S + koff);

        __syncthreads();
        As[kq + 0][lm] = va.x;
        As[kq + 1][lm] = va.y;
        As[kq + 2][lm] = va.z;
        As[kq + 3][lm] = va.w;
        Bs[kq + 0][lm] = vb.x;
        Bs[kq + 1][lm] = vb.y;
        Bs[kq + 2][lm] = vb.z;
        Bs[kq + 3][lm] = vb.w;
        __syncthreads();

#pragma unroll
        for (int k = 0; k < 8; k++) {
            float4 a0 = *reinterpret_cast<float4*>(&As[k][tr * 8]);
            float4 a1 = *reinterpret_cast<float4*>(&As[k][tr * 8 + 4]);
            float4 b0 = *reinterpret_cast<float4*>(&Bs[k][tc * 8]);
            float4 b1 = *reinterpret_cast<float4*>(&Bs[k][tc * 8 + 4]);
            float av[8] = {a0.x, a0.y, a0.z, a0.w, a1.x, a1.y, a1.z, a1.w};
            float bv[8] = {b0.x, b0.y, b0.z, b0.w, b1.x, b1.y, b1.z, b1.w};
#pragma unroll
            for (int i = 0; i < 8; i++)
#pragma unroll
                for (int j = 0; j < 8; j++) acc[i][j] += av[i] * bv[j];
        }
    }

    // epilogue: bias + relu
    float4 bb0 = *reinterpret_cast<const float4*>(bias + tc * 8);
    float4 bb1 = *reinterpret_cast<const float4*>(bias + tc * 8 + 4);
    float bb[8] = {bb0.x, bb0.y, bb0.z, bb0.w, bb1.x, bb1.y, bb1.z, bb1.w};
#pragma unroll
    for (int i = 0; i < 8; i++) {
        int n = m0 + tr * 8 + i;
        if (n < M) {
            float4 o0, o1;
            o0.x = fmaxf(acc[i][0] + bb[0], 0.f);
            o0.y = fmaxf(acc[i][1] + bb[1], 0.f);
            o0.z = fmaxf(acc[i][2] + bb[2], 0.f);
            o0.w = fmaxf(acc[i][3] + bb[3], 0.f);
            o1.x = fmaxf(acc[i][4] + bb[4], 0.f);
            o1.y = fmaxf(acc[i][5] + bb[5], 0.f);
            o1.z = fmaxf(acc[i][6] + bb[6], 0.f);
            o1.w = fmaxf(acc[i][7] + bb[7], 0.f);
            *reinterpret_cast<float4*>(C + (size_t)n * HID + tc * 8) = o0;
            *reinterpret_cast<float4*>(C + (size_t)n * HID + tc * 8 + 4) = o1;
        }
    }
}

// ---------------------------------------------------------------
// Final projection: out[n][j] = h[n] . Wh[j] + bh[j], one warp/node.
// ---------------------------------------------------------------
__global__ void final_kernel(const float* __restrict__ h, const float* __restrict__ Wh,
                             const float* __restrict__ bh, float* __restrict__ out, int M) {
    __shared__ float Ws[OUTDIM * HID];
    __shared__ float bs[OUTDIM];
    int tid = threadIdx.x;
    for (int i = tid; i < OUTDIM * HID; i += blockDim.x) Ws[i] = Wh[i];
    if (tid < OUTDIM) bs[tid] = bh[tid];
    __syncthreads();

    int gw = (blockIdx.x * blockDim.x + tid) >> 5;
    int lane = tid & 31;
    if (gw >= M) return;

    float4 hv = *reinterpret_cast<const float4*>(h + (size_t)gw * HID + lane * 4);
#pragma unroll
    for (int j = 0; j < OUTDIM; j++) {
        const float* wr = Ws + j * HID + lane * 4;
        float p = hv.x * wr[0] + hv.y * wr[1] + hv.z * wr[2] + hv.w * wr[3];
#pragma unroll
        for (int off = 16; off > 0; off >>= 1)
            p += __shfl_down_sync(0xffffffffu, p, off);
        if (lane == 0) out[gw * OUTDIM + j] = p + bs[j];
    }
}

// ---------------------------------------------------------------
extern "C" void kernel_launch(void* const* d_in, const int* in_sizes, int n_in,
                              void* d_out, int out_size) {
    (void)n_in; (void)out_size;
    const float* x   = (const float*)d_in[0];
    const int*   ei  = (const int*)d_in[1];
    const float* Wl1 = (const float*)d_in[2];
    const float* Wr1 = (const float*)d_in[3];
    const float* b1  = (const float*)d_in[4];
    const float* Wl2 = (const float*)d_in[5];
    const float* Wr2 = (const float*)d_in[6];
    const float* b2  = (const float*)d_in[7];
    const float* Wl3 = (const float*)d_in[8];
    const float* Wr3 = (const float*)d_in[9];
    const float* b3  = (const float*)d_in[10];
    const float* Wh  = (const float*)d_in[11];
    const float* bh  = (const float*)d_in[12];
    float* out = (float*)d_out;

    const int M = in_sizes[0] / INDIM;   // 50000
    const int E = in_sizes[1] / 2;       // 600000

    float *agg, *hA, *hB;
    int* deg;
    cudaGetSymbolAddress((void**)&agg, g_agg);
    cudaGetSymbolAddress((void**)&hA, g_hA);
    cudaGetSymbolAddress((void**)&hB, g_hB);
    cudaGetSymbolAddress((void**)&deg, g_deg);

    const int T = 256;
    const int NB = (M + SCAN_CHUNK - 1) / SCAN_CHUNK;   // 49 for M=50000

    // ---- CSR build ----
    detect_kernel<<<1, 64>>>(ei);
    zero_i_kernel<<<(M + T - 1) / T, T>>>(deg, M);
    convert_kernel<<<(E + T - 1) / T, T>>>(ei, E);
    scan_phase1<<<NB, 256>>>(M);
    scan_phase2<<<1, MAX_SCAN_BLOCKS>>>(NB, E);
    scan_phase3<<<NB, 256>>>(M, E);
    fill_kernel<<<(E + T - 1) / T, T>>>(E);

    const int gemmBlocks = (M + 127) / 128;

    // ---- layer 1 (16 -> 128) ----
    gather16_kernel<<<((M * 4) + T - 1) / T, T>>>(x, agg, M);
    sage_gemm_kernel<INDIM><<<gemmBlocks, 256>>>(agg, x, Wl1, Wr1, b1, hA, M);

    // ---- layer 2 (128 -> 128) ----
    gather128_kernel<<<((M * 32) + T - 1) / T, T>>>(hA, agg, M);
    sage_gemm_kernel<HID><<<gemmBlocks, 256>>>(agg, hA, Wl2, Wr2, b2, hB, M);

    // ---- layer 3 (128 -> 128) ----
    gather128_kernel<<<((M * 32) + T - 1) / T, T>>>(hB, agg, M);
    sage_gemm_kernel<HID><<<gemmBlocks, 256>>>(agg, hB, Wl3, Wr3, b3, hA, M);

    // ---- final projection (128 -> 4) ----
    final_kernel<<<((M * 32) + T - 1) / T, T>>>(hA, Wh, bh, out, M);
}

// round 5
// speedup vs baseline: 3.4011x; 1.8283x over previous
#include <cuda_runtime.h>
#include <cuda_bf16.h>
#include <cstdint>

#define NN 50000
#define HID 128
#define INDIM 16
#define OUTDIM 4
#define MAXE 600000
#define SCAN_CHUNK 1024
#define MAX_SCAN_BLOCKS 128
#define TSTRIDE 40   // smem tile row stride in bf16 elements (80B -> conflict-free ldmatrix)

// ---- scratch (static device globals; no runtime allocation) ----
__device__ float g_agg[NN * HID];
__device__ float g_hA[NN * HID];
__device__ float g_hB[NN * HID];
__device__ __nv_bfloat16 g_wHi[4][HID * HID];  // Wl2,Wr2,Wl3,Wr3 splits
__device__ __nv_bfloat16 g_wLo[4][HID * HID];
__device__ int   g_src[MAXE];
__device__ int   g_dst[MAXE];
__device__ int   g_csrc[MAXE];
__device__ int   g_deg[NN];
__device__ int   g_rowstart[NN + 1];
__device__ int   g_cursor[NN];
__device__ int   g_blocksum[MAX_SCAN_BLOCKS];
__device__ int   g_blockoff[MAX_SCAN_BLOCKS];
__device__ int   g_is64;

// ================= helpers =================
__device__ __forceinline__ uint32_t smem_u32(const void* p) {
    uint32_t a;
    asm("{ .reg .u64 t; cvta.to.shared.u64 t, %1; cvt.u32.u64 %0, t; }" : "=r"(a) : "l"(p));
    return a;
}

#define LDMX4(r, a)                                                            \
    asm volatile("ldmatrix.sync.aligned.m8n8.x4.shared.b16 {%0,%1,%2,%3}, [%4];" \
                 : "=r"((r)[0]), "=r"((r)[1]), "=r"((r)[2]), "=r"((r)[3])      \
                 : "r"(a))

__device__ __forceinline__ void mma16816(float* c, const uint32_t* a, const uint32_t* b) {
    asm volatile(
        "mma.sync.aligned.m16n8k16.row.col.f32.bf16.bf16.f32 "
        "{%0,%1,%2,%3}, {%4,%5,%6,%7}, {%8,%9}, {%0,%1,%2,%3};"
        : "+f"(c[0]), "+f"(c[1]), "+f"(c[2]), "+f"(c[3])
        : "r"(a[0]), "r"(a[1]), "r"(a[2]), "r"(a[3]), "r"(b[0]), "r"(b[1]));
}

__device__ __forceinline__ void split2(float v, __nv_bfloat16& hi, __nv_bfloat16& lo) {
    hi = __float2bfloat16(v);
    lo = __float2bfloat16(v - __bfloat162float(hi));
}
__device__ __forceinline__ uint32_t pack2(__nv_bfloat16 a, __nv_bfloat16 b) {
    __nv_bfloat162 t = __halves2bfloat162(a, b);
    return *reinterpret_cast<uint32_t*>(&t);
}

// ================= CSR build =================
__global__ void detect_kernel(const int* __restrict__ w) {
    __shared__ int anynz;
    if (threadIdx.x == 0) anynz = 0;
    __syncthreads();
    if (w[2 * threadIdx.x + 1] != 0) atomicOr(&anynz, 1);
    __syncthreads();
    if (threadIdx.x == 0) g_is64 = anynz ? 0 : 1;
}

__global__ void zero_i_kernel(int* __restrict__ p, int n) {
    int i = blockIdx.x * blockDim.x + threadIdx.x;
    if (i < n) p[i] = 0;
}

__global__ void convert_kernel(const int* __restrict__ w, int E) {
    int i = blockIdx.x * blockDim.x + threadIdx.x;
    if (i >= E) return;
    int s, d;
    if (g_is64) { s = w[2 * i]; d = w[2 * (E + i)]; }
    else        { s = w[i];     d = w[E + i];       }
    g_src[i] = s;
    g_dst[i] = d;
    atomicAdd(&g_deg[d], 1);
}

__device__ __forceinline__ void block_scan_1024(int& thread_sum, int& thread_excl, int* warp_buf) {
    int t = threadIdx.x;
    int lane = t & 31, w = t >> 5;
    int v = thread_sum;
#pragma unroll
    for (int off = 1; off < 32; off <<= 1) {
        int u = __shfl_up_sync(0xffffffffu, v, off);
        if (lane >= off) v += u;
    }
    if (lane == 31) warp_buf[w] = v;
    __syncthreads();
    if (w == 0) {
        int ws = (lane < 8) ? warp_buf[lane] : 0;
#pragma unroll
        for (int off = 1; off < 8; off <<= 1) {
            int u = __shfl_up_sync(0xffffffffu, ws, off);
            if (lane >= off) ws += u;
        }
        if (lane < 8) warp_buf[lane] = ws;
    }
    __syncthreads();
    thread_excl = v - thread_sum + (w > 0 ? warp_buf[w - 1] : 0);
}

__global__ void scan_phase1(int M) {
    __shared__ int warp_buf[8];
    int b = blockIdx.x, t = threadIdx.x;
    int base = b * SCAN_CHUNK + t * 4;
    int d[4] = {0, 0, 0, 0};
#pragma unroll
    for (int i = 0; i < 4; i++)
        if (base + i < M) d[i] = g_deg[base + i];
    int s = d[0] + d[1] + d[2] + d[3];
    int excl;
    block_scan_1024(s, excl, warp_buf);
    if (t == blockDim.x - 1) g_blocksum[b] = excl + s;
}

__global__ void scan_phase2(int NB) {
    __shared__ int buf[MAX_SCAN_BLOCKS];
    int t = threadIdx.x;
    if (t < NB) buf[t] = g_blocksum[t];
    __syncthreads();
    if (t == 0) {
        int run = 0;
        for (int i = 0; i < NB; i++) { int x = buf[i]; buf[i] = run; run += x; }
    }
    __syncthreads();
    if (t < NB) g_blockoff[t] = buf[t];
}

__global__ void scan_phase3(int M, int E) {
    __shared__ int warp_buf[8];
    int b = blockIdx.x, t = threadIdx.x;
    int base = b * SCAN_CHUNK + t * 4;
    int d[4] = {0, 0, 0, 0};
#pragma unroll
    for (int i = 0; i < 4; i++)
        if (base + i < M) d[i] = g_deg[base + i];
    int s = d[0] + d[1] + d[2] + d[3];
    int excl;
    block_scan_1024(s, excl, warp_buf);
    int run = excl + g_blockoff[b];
#pragma unroll
    for (int i = 0; i < 4; i++) {
        if (base + i < M) {
            g_rowstart[base + i] = run;
            g_cursor[base + i] = run;
            run += d[i];
        }
    }
    if (b == 0 && t == 0) g_rowstart[M] = E;
}

__global__ void fill_kernel(int E) {
    int i = blockIdx.x * blockDim.x + threadIdx.x;
    if (i >= E) return;
    int d = g_dst[i];
    int pos = atomicAdd(&g_cursor[d], 1);
    g_csrc[pos] = g_src[i];
}

// ================= weight split =================
__global__ void wsplit_kernel(const float* __restrict__ w, __nv_bfloat16* __restrict__ hi,
                              __nv_bfloat16* __restrict__ lo, int n) {
    int i = blockIdx.x * blockDim.x + threadIdx.x;
    if (i >= n) return;
    __nv_bfloat16 h, l;
    split2(w[i], h, l);
    hi[i] = h;
    lo[i] = l;
}

// ================= gathers (fp32, CSR) =================
__global__ void gather128_kernel(const float* __restrict__ h, float* __restrict__ agg, int M) {
    int gt = blockIdx.x * blockDim.x + threadIdx.x;
    int n = gt >> 5;
    if (n >= M) return;
    int lane = gt & 31;
    int rs0 = g_rowstart[n], rs1 = g_rowstart[n + 1];
    float4 acc = make_float4(0.f, 0.f, 0.f, 0.f);
    int i = rs0;
    for (; i + 4 <= rs1; i += 4) {
        int s0 = g_csrc[i + 0];
        int s1 = g_csrc[i + 1];
        int s2 = g_csrc[i + 2];
        int s3 = g_csrc[i + 3];
        float4 v0 = __ldg(reinterpret_cast<const float4*>(h + (size_t)s0 * HID) + lane);
        float4 v1 = __ldg(reinterpret_cast<const float4*>(h + (size_t)s1 * HID) + lane);
        float4 v2 = __ldg(reinterpret_cast<const float4*>(h + (size_t)s2 * HID) + lane);
        float4 v3 = __ldg(reinterpret_cast<const float4*>(h + (size_t)s3 * HID) + lane);
        acc.x += v0.x + v1.x + v2.x + v3.x;
        acc.y += v0.y + v1.y + v2.y + v3.y;
        acc.z += v0.z + v1.z + v2.z + v3.z;
        acc.w += v0.w + v1.w + v2.w + v3.w;
    }
    for (; i < rs1; i++) {
        int s0 = g_csrc[i];
        float4 v0 = __ldg(reinterpret_cast<const float4*>(h + (size_t)s0 * HID) + lane);
        acc.x += v0.x; acc.y += v0.y; acc.z += v0.z; acc.w += v0.w;
    }
    float sc = 1.0f / (float)max(rs1 - rs0, 1);
    acc.x *= sc; acc.y *= sc; acc.z *= sc; acc.w *= sc;
    reinterpret_cast<float4*>(agg + (size_t)n * HID)[lane] = acc;
}

__global__ void gather16_kernel(const float* __restrict__ x, float* __restrict__ agg, int M) {
    int gt = blockIdx.x * blockDim.x + threadIdx.x;
    int n = gt >> 2;
    if (n >= M) return;
    int q = gt & 3;
    int rs0 = g_rowstart[n], rs1 = g_rowstart[n + 1];
    float4 acc = make_float4(0.f, 0.f, 0.f, 0.f);
    for (int i = rs0; i < rs1; i++) {
        int s0 = g_csrc[i];
        float4 v = __ldg(reinterpret_cast<const float4*>(x + (size_t)s0 * INDIM) + q);
        acc.x += v.x; acc.y += v.y; acc.z += v.z; acc.w += v.w;
    }
    float sc = 1.0f / (float)max(rs1 - rs0, 1);
    acc.x *= sc; acc.y *= sc; acc.z *= sc; acc.w *= sc;
    reinterpret_cast<float4*>(agg + (size_t)n * INDIM)[q] = acc;
}

// ================= layer-1 FFMA GEMM (K=32) =================
template <int S>
__global__ void __launch_bounds__(256)
sage_gemm_kernel(const float* __restrict__ A0, const float* __restrict__ A1,
                 const float* __restrict__ W0, const float* __restrict__ W1,
                 const float* __restrict__ bias, float* __restrict__ C, int M) {
    __shared__ float As[8][128];
    __shared__ float Bs[8][128];

    const int tid = threadIdx.x;
    const int m0 = blockIdx.x * 128;
    const int lm = tid >> 1;
    const int kq = (tid & 1) * 4;
    const int node = m0 + lm;
    const int tr = tid >> 4;
    const int tc = tid & 15;

    float acc[8][8];
#pragma unroll
    for (int i = 0; i < 8; i++)
#pragma unroll
        for (int j = 0; j < 8; j++) acc[i][j] = 0.f;

    const int K = 2 * S;
#pragma unroll 2
    for (int k0 = 0; k0 < K; k0 += 8) {
        const bool half = (k0 >= S);
        const float* Ab = half ? A1 : A0;
        const float* Wb = half ? W1 : W0;
        const int koff = (half ? k0 - S : k0) + kq;

        float4 va = make_float4(0.f, 0.f, 0.f, 0.f);
        if (node < M)
            va = *reinterpret_cast<const float4*>(Ab + (size_t)node * S + koff);
        float4 vb = *reinterpret_cast<const float4*>(Wb + (size_t)lm * S + koff);

        __syncthreads();
        As[kq + 0][lm] = va.x;
        As[kq + 1][lm] = va.y;
        As[kq + 2][lm] = va.z;
        As[kq + 3][lm] = va.w;
        Bs[kq + 0][lm] = vb.x;
        Bs[kq + 1][lm] = vb.y;
        Bs[kq + 2][lm] = vb.z;
        Bs[kq + 3][lm] = vb.w;
        __syncthreads();

#pragma unroll
        for (int k = 0; k < 8; k++) {
            float4 a0 = *reinterpret_cast<float4*>(&As[k][tr * 8]);
            float4 a1 = *reinterpret_cast<float4*>(&As[k][tr * 8 + 4]);
            float4 b0 = *reinterpret_cast<float4*>(&Bs[k][tc * 8]);
            float4 b1 = *reinterpret_cast<float4*>(&Bs[k][tc * 8 + 4]);
            float av[8] = {a0.x, a0.y, a0.z, a0.w, a1.x, a1.y, a1.z, a1.w};
            float bv[8] = {b0.x, b0.y, b0.z, b0.w, b1.x, b1.y, b1.z, b1.w};
#pragma unroll
            for (int i = 0; i < 8; i++)
#pragma unroll
                for (int j = 0; j < 8; j++) acc[i][j] += av[i] * bv[j];
        }
    }

    float4 bb0 = *reinterpret_cast<const float4*>(bias + tc * 8);
    float4 bb1 = *reinterpret_cast<const float4*>(bias + tc * 8 + 4);
    float bb[8] = {bb0.x, bb0.y, bb0.z, bb0.w, bb1.x, bb1.y, bb1.z, bb1.w};
#pragma unroll
    for (int i = 0; i < 8; i++) {
        int n = m0 + tr * 8 + i;
        if (n < M) {
            float4 o0, o1;
            o0.x = fmaxf(acc[i][0] + bb[0], 0.f);
            o0.y = fmaxf(acc[i][1] + bb[1], 0.f);
            o0.z = fmaxf(acc[i][2] + bb[2], 0.f);
            o0.w = fmaxf(acc[i][3] + bb[3], 0.f);
            o1.x = fmaxf(acc[i][4] + bb[4], 0.f);
            o1.y = fmaxf(acc[i][5] + bb[5], 0.f);
            o1.z = fmaxf(acc[i][6] + bb[6], 0.f);
            o1.w = fmaxf(acc[i][7] + bb[7], 0.f);
            *reinterpret_cast<float4*>(C + (size_t)n * HID + tc * 8) = o0;
            *reinterpret_cast<float4*>(C + (size_t)n * HID + tc * 8 + 4) = o1;
        }
    }
}

// ================= tensor-core SAGE GEMM (layers 2/3) via mma.sync =================
// C[n][j] = relu( agg[n,:].W0[j,:] + h[n,:].W1[j,:] + bias[j] ),  K = 2*128.
// bf16 hi/lo split, 3 products. Block 128x128, 8 warps of 32x64, K-chunks of 32.
__global__ void __launch_bounds__(256)
tensor_sage_kernel(const float* __restrict__ A0, const float* __restrict__ A1,
                   const __nv_bfloat16* __restrict__ W0hi, const __nv_bfloat16* __restrict__ W0lo,
                   const __nv_bfloat16* __restrict__ W1hi, const __nv_bfloat16* __restrict__ W1lo,
                   const float* __restrict__ bias, float* __restrict__ C, int M) {
    __shared__ __nv_bfloat16 sAhi[128 * TSTRIDE];
    __shared__ __nv_bfloat16 sAlo[128 * TSTRIDE];
    __shared__ __nv_bfloat16 sBhi[128 * TSTRIDE];
    __shared__ __nv_bfloat16 sBlo[128 * TSTRIDE];

    const int tid = threadIdx.x;
    const int wid = tid >> 5;
    const int lane = tid & 31;
    const int wm = wid & 3;      // warp row tile: rows wm*32 .. +31
    const int wn = wid >> 2;     // warp col tile: cols wn*64 .. +63
    const int m0 = blockIdx.x * 128;

    const uint32_t uAhi = smem_u32(sAhi);
    const uint32_t uAlo = smem_u32(sAlo);
    const uint32_t uBhi = smem_u32(sBhi);
    const uint32_t uBlo = smem_u32(sBlo);

    float acc[2][8][4];
#pragma unroll
    for (int i = 0; i < 2; i++)
#pragma unroll
        for (int j = 0; j < 8; j++)
#pragma unroll
            for (int k = 0; k < 4; k++) acc[i][j][k] = 0.f;

    // ldmatrix source addresses (fixed per thread, offset per k-step/tile)
    const int arow = wm * 32 + (lane & 15);
    const int akof = (lane & 16) ? 8 : 0;
    const int nrow0 = wn * 64 + (lane & 7) + ((lane & 16) ? 8 : 0);
    const int nkof = (lane & 8) ? 8 : 0;

#pragma unroll
    for (int chunk = 0; chunk < 8; chunk++) {
        const float* A = (chunk < 4) ? A0 : A1;
        const __nv_bfloat16* WH = (chunk < 4) ? W0hi : W1hi;
        const __nv_bfloat16* WL = (chunk < 4) ? W0lo : W1lo;
        const int koff = (chunk & 3) * 32;

        __syncthreads();
        // ---- load A (fp32 -> split bf16 hi/lo into smem), 128 rows x 32 k ----
#pragma unroll
        for (int i = 0; i < 4; i++) {
            int u = tid + i * 256;            // 1024 float4 units
            int row = u >> 3;
            int q = (u & 7) * 4;
            float4 v = make_float4(0.f, 0.f, 0.f, 0.f);
            int node = m0 + row;
            if (node < M)
                v = *reinterpret_cast<const float4*>(A + (size_t)node * HID + koff + q);
            __nv_bfloat16 h0, l0, h1, l1, h2, l2, h3, l3;
            split2(v.x, h0, l0);
            split2(v.y, h1, l1);
            split2(v.z, h2, l2);
            split2(v.w, h3, l3);
            int so = row * TSTRIDE + q;
            uint2 ph, pl;
            ph.x = pack2(h0, h1); ph.y = pack2(h2, h3);
            pl.x = pack2(l0, l1); pl.y = pack2(l2, l3);
            *reinterpret_cast<uint2*>(sAhi + so) = ph;
            *reinterpret_cast<uint2*>(sAlo + so) = pl;
        }
        // ---- load B (bf16 hi/lo), 128 rows x 32 k ----
#pragma unroll
        for (int i = 0; i < 2; i++) {
            int u = tid + i * 256;            // 512 uint4 units
            int row = u >> 2;
            int c = (u & 3) * 8;
            uint4 vh = *reinterpret_cast<const uint4*>(WH + (size_t)row * HID + koff + c);
            uint4 vl = *reinterpret_cast<const uint4*>(WL + (size_t)row * HID + koff + c);
            int so = row * TSTRIDE + c;
            *reinterpret_cast<uint4*>(sBhi + so) = vh;
            *reinterpret_cast<uint4*>(sBlo + so) = vl;
        }
        __syncthreads();

        // ---- 2 k-steps of 16 ----
#pragma unroll
        for (int ks = 0; ks < 2; ks++) {
            const int k0 = ks * 16;
            uint32_t ahi[2][4], alo[2][4];
#pragma unroll
            for (int mi = 0; mi < 2; mi++) {
                uint32_t off = ((arow + mi * 16) * TSTRIDE + k0 + akof) * 2;
                LDMX4(ahi[mi], uAhi + off);
                LDMX4(alo[mi], uAlo + off);
            }
#pragma unroll
            for (int np = 0; np < 4; np++) {
                uint32_t boff = ((nrow0 + np * 16) * TSTRIDE + k0 + nkof) * 2;
                uint32_t bh[4], bl[4];
                LDMX4(bh, uBhi + boff);
                LDMX4(bl, uBlo + boff);
#pragma unroll
                for (int mi = 0; mi < 2; mi++) {
#pragma unroll
                    for (int na = 0; na < 2; na++) {
                        float* c = acc[mi][np * 2 + na];
                        mma16816(c, ahi[mi], &bh[na * 2]);
                        mma16816(c, ahi[mi], &bl[na * 2]);
                        mma16816(c, alo[mi], &bh[na * 2]);
                    }
                }
            }
        }
    }

    // ---- epilogue: bias + relu, direct fp32 stores ----
#pragma unroll
    for (int mi = 0; mi < 2; mi++) {
        int row0 = m0 + wm * 32 + mi * 16 + (lane >> 2);
        int row1 = row0 + 8;
#pragma unroll
        for (int ni = 0; ni < 8; ni++) {
            int col = wn * 64 + ni * 8 + 2 * (lane & 3);
            float b0 = __ldg(bias + col);
            float b1 = __ldg(bias + col + 1);
            float* c = acc[mi][ni];
            if (row0 < M) {
                float2 v;
                v.x = fmaxf(c[0] + b0, 0.f);
                v.y = fmaxf(c[1] + b1, 0.f);
                *reinterpret_cast<float2*>(C + (size_t)row0 * HID + col) = v;
            }
            if (row1 < M) {
                float2 v;
                v.x = fmaxf(c[2] + b0, 0.f);
                v.y = fmaxf(c[3] + b1, 0.f);
                *reinterpret_cast<float2*>(C + (size_t)row1 * HID + col) = v;
            }
        }
    }
}

// ================= final projection =================
__global__ void final_kernel(const float* __restrict__ h, const float* __restrict__ Wh,
                             const float* __restrict__ bh, float* __restrict__ out, int M) {
    __shared__ float Ws[OUTDIM * HID];
    __shared__ float bs[OUTDIM];
    int tid = threadIdx.x;
    for (int i = tid; i < OUTDIM * HID; i += blockDim.x) Ws[i] = Wh[i];
    if (tid < OUTDIM) bs[tid] = bh[tid];
    __syncthreads();

    int gw = (blockIdx.x * blockDim.x + tid) >> 5;
    int lane = tid & 31;
    if (gw >= M) return;

    float4 hv = *reinterpret_cast<const float4*>(h + (size_t)gw * HID + lane * 4);
#pragma unroll
    for (int j = 0; j < OUTDIM; j++) {
        const float* wr = Ws + j * HID + lane * 4;
        float p = hv.x * wr[0] + hv.y * wr[1] + hv.z * wr[2] + hv.w * wr[3];
#pragma unroll
        for (int off = 16; off > 0; off >>= 1)
            p += __shfl_down_sync(0xffffffffu, p, off);
        if (lane == 0) out[gw * OUTDIM + j] = p + bs[j];
    }
}

// ---------------------------------------------------------------
extern "C" void kernel_launch(void* const* d_in, const int* in_sizes, int n_in,
                              void* d_out, int out_size) {
    (void)n_in; (void)out_size;
    const float* x   = (const float*)d_in[0];
    const int*   ei  = (const int*)d_in[1];
    const float* Wl1 = (const float*)d_in[2];
    const float* Wr1 = (const float*)d_in[3];
    const float* b1  = (const float*)d_in[4];
    const float* Wl2 = (const float*)d_in[5];
    const float* Wr2 = (const float*)d_in[6];
    const float* b2  = (const float*)d_in[7];
    const float* Wl3 = (const float*)d_in[8];
    const float* Wr3 = (const float*)d_in[9];
    const float* b3  = (const float*)d_in[10];
    const float* Wh  = (const float*)d_in[11];
    const float* bh  = (const float*)d_in[12];
    float* out = (float*)d_out;

    const int M = in_sizes[0] / INDIM;   // 50000
    const int E = in_sizes[1] / 2;       // 600000

    float *agg, *hA, *hB;
    int* deg;
    __nv_bfloat16 *wHi, *wLo;
    cudaGetSymbolAddress((void**)&agg, g_agg);
    cudaGetSymbolAddress((void**)&hA, g_hA);
    cudaGetSymbolAddress((void**)&hB, g_hB);
    cudaGetSymbolAddress((void**)&deg, g_deg);
    cudaGetSymbolAddress((void**)&wHi, g_wHi);
    cudaGetSymbolAddress((void**)&wLo, g_wLo);

    const int T = 256;
    const int NB = (M + SCAN_CHUNK - 1) / SCAN_CHUNK;

    // ---- CSR build ----
    detect_kernel<<<1, 64>>>(ei);
    zero_i_kernel<<<(M + T - 1) / T, T>>>(deg, M);
    convert_kernel<<<(E + T - 1) / T, T>>>(ei, E);
    scan_phase1<<<NB, 256>>>(M);
    scan_phase2<<<1, MAX_SCAN_BLOCKS>>>(NB);
    scan_phase3<<<NB, 256>>>(M, E);
    fill_kernel<<<(E + T - 1) / T, T>>>(E);

    // ---- weight splits (overlaps CSR build on same stream order, tiny) ----
    const int WN = HID * HID;
    wsplit_kernel<<<(WN + T - 1) / T, T>>>(Wl2, wHi + 0 * WN, wLo + 0 * WN, WN);
    wsplit_kernel<<<(WN + T - 1) / T, T>>>(Wr2, wHi + 1 * WN, wLo + 1 * WN, WN);
    wsplit_kernel<<<(WN + T - 1) / T, T>>>(Wl3, wHi + 2 * WN, wLo + 2 * WN, WN);
    wsplit_kernel<<<(WN + T - 1) / T, T>>>(Wr3, wHi + 3 * WN, wLo + 3 * WN, WN);

    const int gemmBlocks = (M + 127) / 128;

    // ---- layer 1 (16 -> 128), FFMA ----
    gather16_kernel<<<((M * 4) + T - 1) / T, T>>>(x, agg, M);
    sage_gemm_kernel<INDIM><<<gemmBlocks, 256>>>(agg, x, Wl1, Wr1, b1, hA, M);

    // ---- layer 2 (128 -> 128), mma.sync ----
    gather128_kernel<<<((M * 32) + T - 1) / T, T>>>(hA, agg, M);
    tensor_sage_kernel<<<gemmBlocks, 256>>>(agg, hA,
        wHi + 0 * WN, wLo + 0 * WN, wHi + 1 * WN, wLo + 1 * WN, b2, hB, M);

    // ---- layer 3 (128 -> 128), mma.sync ----
    gather128_kernel<<<((M * 32) + T - 1) / T, T>>>(hB, agg, M);
    tensor_sage_kernel<<<gemmBlocks, 256>>>(agg, hB,
        wHi + 2 * WN, wLo + 2 * WN, wHi + 3 * WN, wLo + 3 * WN, b3, hA, M);

    // ---- final projection (128 -> 4) ----
    final_kernel<<<((M * 32) + T - 1) / T, T>>>(hA, Wh, bh, out, M);
}